// round 4
// baseline (speedup 1.0000x reference)
#include <cuda_runtime.h>
#include <stdint.h>

// GINEConv: out[n] = (1+eps)*node_feat[n] + sum_{e: dst[e]==n} relu(node_feat[src[e]] + edge_feat[e])
// N=50000, E=1600000, D=32 (f32). Indices are int32 (JAX x64 disabled).

#define NN  50000
#define DF  32
#define CAP 128   // degree ~ Poisson(32), max ~66 -> large safety margin

// Scratch as __device__ globals. g_cnt zero-initialized at module load; k_gather
// self-resets it so the invariant holds across graph replays. g_bucket contents
// are always valid int pairs (zero-init or stale in-range values), so reading
// slots beyond cnt (but < CAP) is memory-safe; accumulation is masked.
__device__ int  g_cnt[NN];
__device__ int2 g_bucket[(size_t)NN * CAP];   // (edge_id, src) pairs

__global__ void k_scatter(const int* __restrict__ src,
                          const int* __restrict__ dst,
                          int E) {
    int t = blockIdx.x * blockDim.x + threadIdx.x;
    int e = t * 2;
    if (e >= E) return;
    int2 s2 = *(const int2*)(src + e);
    int2 d2 = *(const int2*)(dst + e);

    if ((unsigned)d2.x < NN) {
        int slot = atomicAdd(&g_cnt[d2.x], 1);
        if (slot < CAP) g_bucket[(size_t)d2.x * CAP + slot] = make_int2(e, s2.x);
    }
    if (e + 1 < E && (unsigned)d2.y < NN) {
        int slot = atomicAdd(&g_cnt[d2.y], 1);
        if (slot < CAP) g_bucket[(size_t)d2.y * CAP + slot] = make_int2(e + 1, s2.y);
    }
}

// Warp-per-node gather. lane = g*8 + f: g = edge subgroup (4 edges in flight),
// f = float4 column. No shfls: each lane loads the pairs it needs directly
// (4 distinct int2 per step -> one 32B wavefront, L1/L2 resident).
// All global loads are unconditional and front-batched; only the accumulate
// is masked, so MLP per warp is ~12 independent loads per unrolled block.
__global__ void k_gather(const float4* __restrict__ node_feat,   // [N, 8] float4
                         const float4* __restrict__ edge_feat,   // [E, 8] float4
                         const float* __restrict__ eps,
                         float4* __restrict__ out,               // [N, 8] float4
                         int N) {
    int gwarp = (blockIdx.x * blockDim.x + threadIdx.x) >> 5;
    int lane  = threadIdx.x & 31;
    if (gwarp >= N) return;

    int cnt = g_cnt[gwarp];
    if (lane == 0) g_cnt[gwarp] = 0;       // self-reset for next replay
    cnt = min(cnt, CAP);

    const int f = lane & 7;
    const int g = lane >> 3;

    const int2* bk = g_bucket + (size_t)gwarp * CAP;
    float4 acc = make_float4(0.f, 0.f, 0.f, 0.f);

    // 16 edges per outer iteration; inner fully unrolled with fixed trip count.
    for (int i0 = 0; i0 < cnt; i0 += 16) {
        #pragma unroll
        for (int u = 0; u < 4; u++) {
            int idx = i0 + u * 4 + g;                  // always < CAP (i0<=112, u*4+g<=15)
            int2 p = bk[idx];                          // unconditional, safe
            float4 ef = edge_feat[(size_t)p.x * 8 + f];
            float4 nf = node_feat[(size_t)p.y * 8 + f];
            if (idx < cnt) {
                acc.x += fmaxf(ef.x + nf.x, 0.f);
                acc.y += fmaxf(ef.y + nf.y, 0.f);
                acc.z += fmaxf(ef.z + nf.z, 0.f);
                acc.w += fmaxf(ef.w + nf.w, 0.f);
            }
        }
    }

    // Merge the 4 edge subgroups (lanes l, l^8, l^16, l^24 share f).
    acc.x += __shfl_xor_sync(0xffffffffu, acc.x, 8);
    acc.y += __shfl_xor_sync(0xffffffffu, acc.y, 8);
    acc.z += __shfl_xor_sync(0xffffffffu, acc.z, 8);
    acc.w += __shfl_xor_sync(0xffffffffu, acc.w, 8);
    acc.x += __shfl_xor_sync(0xffffffffu, acc.x, 16);
    acc.y += __shfl_xor_sync(0xffffffffu, acc.y, 16);
    acc.z += __shfl_xor_sync(0xffffffffu, acc.z, 16);
    acc.w += __shfl_xor_sync(0xffffffffu, acc.w, 16);

    if (lane < 8) {   // g == 0 holds the full sum; 8 lanes store the 128B row
        float4 self = node_feat[(size_t)gwarp * 8 + f];
        float k = 1.0f + eps[0];
        out[(size_t)gwarp * 8 + f] = make_float4(k * self.x + acc.x,
                                                 k * self.y + acc.y,
                                                 k * self.z + acc.z,
                                                 k * self.w + acc.w);
    }
}

extern "C" void kernel_launch(void* const* d_in, const int* in_sizes, int n_in,
                              void* d_out, int out_size) {
    const float4* node_feat = (const float4*)d_in[0];  // [N, 32] f32
    const float4* edge_feat = (const float4*)d_in[1];  // [E, 32] f32
    const float*  eps       = (const float*)d_in[2];   // [1]
    const int*    src       = (const int*)d_in[3];     // [E] int32
    const int*    dst       = (const int*)d_in[4];     // [E] int32
    float4* out = (float4*)d_out;

    int N = in_sizes[0] / DF;   // 50000
    int E = in_sizes[3];        // 1600000

    int sthreads = (E + 1) / 2;
    k_scatter<<<(sthreads + 255) / 256, 256>>>(src, dst, E);

    long long gthreads = (long long)N * 32;
    k_gather<<<(int)((gthreads + 255) / 256), 256>>>(node_feat, edge_feat, eps, out, N);
}

// round 5
// speedup vs baseline: 1.0502x; 1.0502x over previous
#include <cuda_runtime.h>
#include <stdint.h>

// GINEConv: out[n] = (1+eps)*node_feat[n] + sum_{e: dst[e]==n} relu(node_feat[src[e]] + edge_feat[e])
// N=50000, E=1600000, D=32 (f32). Indices int32.
//
// Strategy: scatter finished MESSAGES (random full-line WRITES, fire-and-forget)
// into per-dst buckets, then stream-sum contiguous bucket rows per node.
// No random reads of edge data, no float atomics.

#define NN  50000
#define DF  32
#define CAP 80    // degree ~ Poisson(32); max ~58 expected -> +8.5 sigma headroom

// g_cnt zero-initialized at module load; k_sum self-resets it each replay.
__device__ int    g_cnt[NN];
__device__ float4 g_msg[(size_t)NN * CAP * 8];   // [node][slot][8xfloat4] = 512 MB scratch

// Phase A: warp = 4 edges. lane = g*8 + f (g: edge subgroup, f: float4 column).
// edge_feat read is 512B contiguous per warp instruction; node_feat row is an
// 8-lane broadcast gather (L2-resident); message store is one full random 128B
// line per subgroup (no read-for-ownership, no latency exposure).
__global__ void k_msg(const float4* __restrict__ node_feat,
                      const float4* __restrict__ edge_feat,
                      const int* __restrict__ src,
                      const int* __restrict__ dst,
                      int E) {
    int warp = (blockIdx.x * blockDim.x + threadIdx.x) >> 5;
    int lane = threadIdx.x & 31;
    int f = lane & 7;
    int g = lane >> 3;

    int e = warp * 4 + g;
    if (e >= E) return;

    // slot assignment by subgroup leader
    int off = 0;
    if (f == 0) {
        int d = dst[e];
        int slot = atomicAdd(&g_cnt[d], 1);
        if (slot >= CAP) slot = CAP - 1;   // lossy clamp; statistically unreachable
        off = d * CAP + slot;
    }
    off = __shfl_sync(0xffffffffu, off, lane & ~7);   // broadcast within subgroup

    int s = src[e];                                    // 8-lane same-address broadcast load

    float4 ef = edge_feat[(size_t)e * 8 + f];          // contiguous stream
    float4 nf = node_feat[(size_t)s * 8 + f];          // L2 hit
    float4 m = make_float4(fmaxf(ef.x + nf.x, 0.f),
                           fmaxf(ef.y + nf.y, 0.f),
                           fmaxf(ef.z + nf.z, 0.f),
                           fmaxf(ef.w + nf.w, 0.f));
    g_msg[(size_t)off * 8 + f] = m;                    // random full-line write
}

// Phase B: warp per node; contiguous streaming read of its message rows.
__global__ void k_sum(const float4* __restrict__ node_feat,
                      const float* __restrict__ eps,
                      float4* __restrict__ out,
                      int N) {
    int n    = (blockIdx.x * blockDim.x + threadIdx.x) >> 5;
    int lane = threadIdx.x & 31;
    if (n >= N) return;

    int cnt = g_cnt[n];
    if (lane == 0) g_cnt[n] = 0;       // self-reset for next graph replay
    cnt = min(cnt, CAP);

    int f = lane & 7;
    int g = lane >> 3;

    const float4* rows = g_msg + (size_t)n * CAP * 8;
    float4 acc = make_float4(0.f, 0.f, 0.f, 0.f);

    // 8 rows per outer iteration, loads unconditional (idx < CAP always),
    // accumulation masked; addresses are purely sequential -> max MLP.
    for (int i0 = 0; i0 < cnt; i0 += 8) {
        #pragma unroll
        for (int u = 0; u < 2; u++) {
            int idx = i0 + u * 4 + g;                  // <= 72+7 = 79 < CAP
            float4 v = rows[(size_t)idx * 8 + f];
            if (idx < cnt) {
                acc.x += v.x; acc.y += v.y; acc.z += v.z; acc.w += v.w;
            }
        }
    }

    // merge the 4 edge subgroups (lanes l, l^8, l^16, l^24 share column f)
    acc.x += __shfl_xor_sync(0xffffffffu, acc.x, 8);
    acc.y += __shfl_xor_sync(0xffffffffu, acc.y, 8);
    acc.z += __shfl_xor_sync(0xffffffffu, acc.z, 8);
    acc.w += __shfl_xor_sync(0xffffffffu, acc.w, 8);
    acc.x += __shfl_xor_sync(0xffffffffu, acc.x, 16);
    acc.y += __shfl_xor_sync(0xffffffffu, acc.y, 16);
    acc.z += __shfl_xor_sync(0xffffffffu, acc.z, 16);
    acc.w += __shfl_xor_sync(0xffffffffu, acc.w, 16);

    if (lane < 8) {
        float4 self = node_feat[(size_t)n * 8 + f];
        float k = 1.0f + eps[0];
        out[(size_t)n * 8 + f] = make_float4(k * self.x + acc.x,
                                             k * self.y + acc.y,
                                             k * self.z + acc.z,
                                             k * self.w + acc.w);
    }
}

extern "C" void kernel_launch(void* const* d_in, const int* in_sizes, int n_in,
                              void* d_out, int out_size) {
    const float4* node_feat = (const float4*)d_in[0];  // [N, 32] f32
    const float4* edge_feat = (const float4*)d_in[1];  // [E, 32] f32
    const float*  eps       = (const float*)d_in[2];   // [1]
    const int*    src       = (const int*)d_in[3];     // [E] int32
    const int*    dst       = (const int*)d_in[4];     // [E] int32
    float4* out = (float4*)d_out;

    int N = in_sizes[0] / DF;   // 50000
    int E = in_sizes[3];        // 1600000

    // Phase A: compute + scatter messages (random writes, streaming reads)
    long long athreads = ((long long)(E + 3) / 4) * 32;
    k_msg<<<(int)((athreads + 255) / 256), 256>>>(node_feat, edge_feat, src, dst, E);

    // Phase B: streaming per-node sum + fused eps-residual + counter reset
    long long bthreads = (long long)N * 32;
    k_sum<<<(int)((bthreads + 255) / 256), 256>>>(node_feat, eps, out, N);
}

// round 6
// speedup vs baseline: 2.6230x; 2.4975x over previous
#include <cuda_runtime.h>
#include <stdint.h>

// GINEConv: out[n] = (1+eps)*node_feat[n] + sum_{e: dst[e]==n} relu(node_feat[src[e]] + edge_feat[e])
// N=50000, E=1600000, D=32 (f32). Indices int32.
//
// Single-pass strategy: init out with the eps-residual, then stream edges and
// scatter each finished message row into out[dst] with red.global.add.v4.f32
// (sm_90+ 128-bit vector reduction). No scratch, no message round-trip.

#define DF 32

// out = (1+eps) * node_feat   (also un-poisons d_out)
__global__ void k_init(const float4* __restrict__ node_feat,
                       const float* __restrict__ eps,
                       float4* __restrict__ out,
                       int n4) {                       // N*8 float4 elements
    int i = blockIdx.x * blockDim.x + threadIdx.x;
    if (i >= n4) return;
    float k = 1.0f + eps[0];
    float4 v = node_feat[i];
    out[i] = make_float4(k * v.x, k * v.y, k * v.z, k * v.w);
}

// warp = 4 edges; lane = g*8 + f (g: edge subgroup, f: float4 column).
// edge_feat read: 512B contiguous per warp. node_feat[src]: L2-resident gather.
// Output: one vector reduction per lane, fire-and-forget.
__global__ void k_edge(const float4* __restrict__ node_feat,
                       const float4* __restrict__ edge_feat,
                       const int* __restrict__ src,
                       const int* __restrict__ dst,
                       float4* __restrict__ out,
                       int E) {
    int warp = (blockIdx.x * blockDim.x + threadIdx.x) >> 5;
    int lane = threadIdx.x & 31;
    int f = lane & 7;
    int g = lane >> 3;

    int e = warp * 4 + g;
    if (e >= E) return;

    int s = src[e];   // 8-lane broadcast load
    int d = dst[e];   // 8-lane broadcast load

    float4 ef = edge_feat[(size_t)e * 8 + f];   // contiguous stream
    float4 nf = node_feat[(size_t)s * 8 + f];   // L2 hit (6.4 MB working set)

    float mx = fmaxf(ef.x + nf.x, 0.f);
    float my = fmaxf(ef.y + nf.y, 0.f);
    float mz = fmaxf(ef.z + nf.z, 0.f);
    float mw = fmaxf(ef.w + nf.w, 0.f);

    float4* dstp = out + (size_t)d * 8 + f;
    asm volatile("red.global.add.v4.f32 [%0], {%1, %2, %3, %4};"
                 :: "l"(dstp), "f"(mx), "f"(my), "f"(mz), "f"(mw)
                 : "memory");
}

extern "C" void kernel_launch(void* const* d_in, const int* in_sizes, int n_in,
                              void* d_out, int out_size) {
    const float4* node_feat = (const float4*)d_in[0];  // [N, 32] f32
    const float4* edge_feat = (const float4*)d_in[1];  // [E, 32] f32
    const float*  eps       = (const float*)d_in[2];   // [1]
    const int*    src       = (const int*)d_in[3];     // [E] int32
    const int*    dst       = (const int*)d_in[4];     // [E] int32
    float4* out = (float4*)d_out;

    int N = in_sizes[0] / DF;   // 50000
    int E = in_sizes[3];        // 1600000

    // 1) residual init (must precede any reductions; same stream => ordered)
    int n4 = N * 8;
    k_init<<<(n4 + 255) / 256, 256>>>(node_feat, eps, out, n4);

    // 2) edge stream + vector-atomic scatter
    long long threads = ((long long)(E + 3) / 4) * 32;
    k_edge<<<(int)((threads + 255) / 256), 256>>>(node_feat, edge_feat, src, dst, out, E);
}

// round 7
// speedup vs baseline: 3.2593x; 1.2426x over previous
#include <cuda_runtime.h>
#include <stdint.h>

// GINEConv: out[n] = (1+eps)*node_feat[n] + sum_{e: dst[e]==n} relu(node_feat[src[e]] + edge_feat[e])
// N=50000, E=1600000, D=32 (f32). Indices int32.
//
// Single-pass: init out with eps-residual, then stream edges and scatter each
// finished message row into out[dst] via red.global.add.v4.f32 (fire-and-forget).
// R7: 2 edges per thread, front-batched loads (2x MLP), streaming hints on the
// edge stream so L2 stays reserved for the node_feat working set.

#define DF 32

__global__ void k_init(const float4* __restrict__ node_feat,
                       const float* __restrict__ eps,
                       float4* __restrict__ out,
                       int n4) {
    int i = blockIdx.x * blockDim.x + threadIdx.x;
    if (i >= n4) return;
    float k = 1.0f + eps[0];
    float4 v = node_feat[i];
    out[i] = make_float4(k * v.x, k * v.y, k * v.z, k * v.w);
}

// warp = 8 edges; lane = g*8 + f. Each thread owns edges e0 = base+g and
// e1 = e0+4, with all loads front-batched before any compute/RED.
__global__ void k_edge(const float4* __restrict__ node_feat,
                       const float4* __restrict__ edge_feat,
                       const int* __restrict__ src,
                       const int* __restrict__ dst,
                       float4* __restrict__ out,
                       int E) {
    int warp = (blockIdx.x * blockDim.x + threadIdx.x) >> 5;
    int lane = threadIdx.x & 31;
    int f = lane & 7;
    int g = lane >> 3;

    int e0 = warp * 8 + g;
    int e1 = e0 + 4;
    if (e0 >= E) return;
    bool has1 = (e1 < E);
    int e1c = has1 ? e1 : e0;          // clamp: loads stay in-bounds, RED masked

    // ---- front-batched index loads (broadcast within 8-lane subgroup) ----
    int s0 = __ldg(src + e0);
    int d0 = __ldg(dst + e0);
    int s1 = __ldg(src + e1c);
    int d1 = __ldg(dst + e1c);

    // ---- front-batched feature loads: 4 independent 16B loads ----
    float4 ef0 = __ldcs(edge_feat + (size_t)e0  * 8 + f);   // streaming, no reuse
    float4 ef1 = __ldcs(edge_feat + (size_t)e1c * 8 + f);
    float4 nf0 = __ldg (node_feat + (size_t)s0  * 8 + f);   // L2-resident gather
    float4 nf1 = __ldg (node_feat + (size_t)s1  * 8 + f);

    float4 m0 = make_float4(fmaxf(ef0.x + nf0.x, 0.f),
                            fmaxf(ef0.y + nf0.y, 0.f),
                            fmaxf(ef0.z + nf0.z, 0.f),
                            fmaxf(ef0.w + nf0.w, 0.f));
    float4* p0 = out + (size_t)d0 * 8 + f;
    asm volatile("red.global.add.v4.f32 [%0], {%1, %2, %3, %4};"
                 :: "l"(p0), "f"(m0.x), "f"(m0.y), "f"(m0.z), "f"(m0.w)
                 : "memory");

    if (has1) {
        float4 m1 = make_float4(fmaxf(ef1.x + nf1.x, 0.f),
                                fmaxf(ef1.y + nf1.y, 0.f),
                                fmaxf(ef1.z + nf1.z, 0.f),
                                fmaxf(ef1.w + nf1.w, 0.f));
        float4* p1 = out + (size_t)d1 * 8 + f;
        asm volatile("red.global.add.v4.f32 [%0], {%1, %2, %3, %4};"
                     :: "l"(p1), "f"(m1.x), "f"(m1.y), "f"(m1.z), "f"(m1.w)
                     : "memory");
    }
}

extern "C" void kernel_launch(void* const* d_in, const int* in_sizes, int n_in,
                              void* d_out, int out_size) {
    const float4* node_feat = (const float4*)d_in[0];  // [N, 32] f32
    const float4* edge_feat = (const float4*)d_in[1];  // [E, 32] f32
    const float*  eps       = (const float*)d_in[2];   // [1]
    const int*    src       = (const int*)d_in[3];     // [E] int32
    const int*    dst       = (const int*)d_in[4];     // [E] int32
    float4* out = (float4*)d_out;

    int N = in_sizes[0] / DF;   // 50000
    int E = in_sizes[3];        // 1600000

    // 1) residual init (same stream => ordered before reductions)
    int n4 = N * 8;
    k_init<<<(n4 + 255) / 256, 256>>>(node_feat, eps, out, n4);

    // 2) edge stream + vector-atomic scatter, 8 edges per warp
    long long warps = ((long long)E + 7) / 8;
    long long threads = warps * 32;
    k_edge<<<(int)((threads + 255) / 256), 256>>>(node_feat, edge_feat, src, dst, out, E);
}

// round 8
// speedup vs baseline: 3.3937x; 1.0412x over previous
#include <cuda_runtime.h>
#include <stdint.h>

// GINEConv: out[n] = (1+eps)*node_feat[n] + sum_{e: dst[e]==n} relu(node_feat[src[e]] + edge_feat[e])
// N=50000, E=1600000, D=32 (f32). Indices int32.
//
// Single-pass: init out with eps-residual, then stream edges and scatter each
// finished message row into out[dst] via red.global.add.v4.f32 (fire-and-forget).
// R8: 4 edges per thread (warp = 16 edges), all loads front-batched for max MLP.

#define DF 32

__global__ void k_init(const float4* __restrict__ node_feat,
                       const float* __restrict__ eps,
                       float4* __restrict__ out,
                       int n4) {
    int i = blockIdx.x * blockDim.x + threadIdx.x;
    if (i >= n4) return;
    float k = 1.0f + eps[0];
    float4 v = node_feat[i];
    out[i] = make_float4(k * v.x, k * v.y, k * v.z, k * v.w);
}

// warp = 16 edges; lane = g*8 + f. Thread owns edges base+g+4u, u=0..3.
// All index + feature loads issued before any compute; REDs are fire-and-forget.
__global__ void __launch_bounds__(256, 4)
k_edge(const float4* __restrict__ node_feat,
       const float4* __restrict__ edge_feat,
       const int* __restrict__ src,
       const int* __restrict__ dst,
       float4* __restrict__ out,
       int E) {
    int warp = (blockIdx.x * blockDim.x + threadIdx.x) >> 5;
    int lane = threadIdx.x & 31;
    int f = lane & 7;
    int g = lane >> 3;

    int base = warp * 16 + g;
    if (base >= E) return;

    int e[4], ec[4];
    bool has[4];
    #pragma unroll
    for (int u = 0; u < 4; u++) {
        e[u]   = base + 4 * u;
        has[u] = (e[u] < E);
        ec[u]  = has[u] ? e[u] : base;     // clamp keeps loads in-bounds
    }

    // ---- front-batched index loads ----
    int s[4], d[4];
    #pragma unroll
    for (int u = 0; u < 4; u++) {
        s[u] = __ldg(src + ec[u]);
        d[u] = __ldg(dst + ec[u]);
    }

    // ---- front-batched feature loads: 8 independent 16B loads ----
    float4 ef[4], nf[4];
    #pragma unroll
    for (int u = 0; u < 4; u++)
        ef[u] = __ldcs(edge_feat + (size_t)ec[u] * 8 + f);   // streaming, no reuse
    #pragma unroll
    for (int u = 0; u < 4; u++)
        nf[u] = __ldg(node_feat + (size_t)s[u] * 8 + f);     // L2-resident gather

    // ---- compute + fire-and-forget vector reductions ----
    #pragma unroll
    for (int u = 0; u < 4; u++) {
        if (has[u]) {
            float mx = fmaxf(ef[u].x + nf[u].x, 0.f);
            float my = fmaxf(ef[u].y + nf[u].y, 0.f);
            float mz = fmaxf(ef[u].z + nf[u].z, 0.f);
            float mw = fmaxf(ef[u].w + nf[u].w, 0.f);
            float4* p = out + (size_t)d[u] * 8 + f;
            asm volatile("red.global.add.v4.f32 [%0], {%1, %2, %3, %4};"
                         :: "l"(p), "f"(mx), "f"(my), "f"(mz), "f"(mw)
                         : "memory");
        }
    }
}

extern "C" void kernel_launch(void* const* d_in, const int* in_sizes, int n_in,
                              void* d_out, int out_size) {
    const float4* node_feat = (const float4*)d_in[0];  // [N, 32] f32
    const float4* edge_feat = (const float4*)d_in[1];  // [E, 32] f32
    const float*  eps       = (const float*)d_in[2];   // [1]
    const int*    src       = (const int*)d_in[3];     // [E] int32
    const int*    dst       = (const int*)d_in[4];     // [E] int32
    float4* out = (float4*)d_out;

    int N = in_sizes[0] / DF;   // 50000
    int E = in_sizes[3];        // 1600000

    // 1) residual init (same stream => ordered before reductions)
    int n4 = N * 8;
    k_init<<<(n4 + 255) / 256, 256>>>(node_feat, eps, out, n4);

    // 2) edge stream + vector-atomic scatter, 16 edges per warp
    long long warps = ((long long)E + 15) / 16;
    long long threads = warps * 32;
    k_edge<<<(int)((threads + 255) / 256), 256>>>(node_feat, edge_feat, src, dst, out, E);
}